// round 3
// baseline (speedup 1.0000x reference)
#include <cuda_runtime.h>
#include <cstdint>
#include <math.h>

// Problem constants
#define BATCH 32
#define NQ    1024
#define NK    2048
#define DMODEL 256

// GEMM tiling
#define BM 128
#define BN 128
#define BK 32
#define LDSA 36                    // smem row stride (floats), conflict-free
#define TILE_F (128 * LDSA)        // floats per (A or B) tile buffer
#define BUF_STRIDE (2 * TILE_F)    // floats per double-buffer stage (A+B)
#define SMEM_BYTES (2 * BUF_STRIDE * 4)
#define SMEM_BYTES_OUT (SMEM_BYTES + 512)   // + row invS

// Scratch (static device memory — allocation-free per harness rules)
__device__ float g_q   [BATCH * NQ * DMODEL];        // tf32-rounded q
__device__ float g_k   [BATCH * NK * DMODEL];        // tf32-rounded k
__device__ float g_vT  [BATCH * DMODEL * NK];        // v transposed [b][d][k], tf32
__device__ float g_e   [(size_t)BATCH * NQ * NK];    // unnormalized exp(logits) (tf32)
__device__ float g_psum[BATCH * 16 * NQ];            // per (b, ntile, q) partial sum
__device__ float g_rowI[BATCH * NQ];                 // per row 1/sum

__device__ __forceinline__ uint32_t f2tf32(float x) {
    uint32_t r;
    asm("cvt.rna.tf32.f32 %0, %1;" : "=r"(r) : "f"(x));
    return r;
}

__device__ __forceinline__ void mma_tf32(float c[4], const uint32_t a[4], const uint32_t b[2]) {
    asm("mma.sync.aligned.m16n8k8.row.col.f32.tf32.tf32.f32 "
        "{%0,%1,%2,%3}, {%4,%5,%6,%7}, {%8,%9}, {%0,%1,%2,%3};"
        : "+f"(c[0]), "+f"(c[1]), "+f"(c[2]), "+f"(c[3])
        : "r"(a[0]), "r"(a[1]), "r"(a[2]), "r"(a[3]), "r"(b[0]), "r"(b[1]));
}

__device__ __forceinline__ void cp_async16(float* smem, const float* gmem) {
    uint32_t s = (uint32_t)__cvta_generic_to_shared(smem);
    asm volatile("cp.async.cg.shared.global [%0], [%1], 16;" :: "r"(s), "l"(gmem) : "memory");
}
__device__ __forceinline__ void cp_commit() { asm volatile("cp.async.commit_group;" ::: "memory"); }
template<int N> __device__ __forceinline__ void cp_wait() {
    asm volatile("cp.async.wait_group %0;" :: "n"(N) : "memory");
}

// Issue cp.asyncs for one 128x32 A tile and one 128x32 B tile (both [rows][K] layout).
__device__ __forceinline__ void load_tile(const float* a, long long lda,
                                          const float* b, long long ldb,
                                          float* sA, float* sB) {
#pragma unroll
    for (int r = 0; r < 128; r += 32) {
        cp_async16(sA + r * LDSA, a + (long long)r * lda);
        cp_async16(sB + r * LDSA, b + (long long)r * ldb);
    }
    cp_commit();
}

// Fragment compute for one resident 128x32 x 128x32 stage.
template<bool CVT>
__device__ __forceinline__ void mma_stage(const float* cA, const float* cB,
                                          int wm, int wn, int g, int tg,
                                          float (&acc)[2][8][4]) {
#pragma unroll
    for (int kk = 0; kk < BK; kk += 8) {
        uint32_t af[2][4];
#pragma unroll
        for (int mi = 0; mi < 2; mi++) {
            const float* base = cA + (wm * 32 + mi * 16 + g) * LDSA + kk + tg;
            float x0 = base[0];
            float x1 = base[8 * LDSA];
            float x2 = base[4];
            float x3 = base[8 * LDSA + 4];
            af[mi][0] = CVT ? f2tf32(x0) : __float_as_uint(x0);
            af[mi][1] = CVT ? f2tf32(x1) : __float_as_uint(x1);
            af[mi][2] = CVT ? f2tf32(x2) : __float_as_uint(x2);
            af[mi][3] = CVT ? f2tf32(x3) : __float_as_uint(x3);
        }
#pragma unroll
        for (int ni = 0; ni < 8; ni++) {
            uint32_t bf[2];
            const float* base = cB + (wn * 64 + ni * 8 + g) * LDSA + kk + tg;
            float y0 = base[0];
            float y1 = base[4];
            bf[0] = CVT ? f2tf32(y0) : __float_as_uint(y0);
            bf[1] = CVT ? f2tf32(y1) : __float_as_uint(y1);
            mma_tf32(acc[0][ni], af[0], bf);
            mma_tf32(acc[1][ni], af[1], bf);
        }
    }
}

// NT GEMM mainloop: acc[m][n] += sum_k A[m0+m][k] * B[n0+n][k]
template<bool CVT>
__device__ __forceinline__ void gemm_loop(const float* __restrict__ A, long long lda,
                                          const float* __restrict__ B, long long ldb,
                                          int K, int m0, int n0,
                                          float (&acc)[2][8][4], float* smem) {
    const int tid  = threadIdx.x;
    const int warp = tid >> 5, lane = tid & 31;
    const int wm = warp >> 1, wn = warp & 1;
    const int g  = lane >> 2, tg = lane & 3;
    const int lrow = tid >> 3;            // 0..31
    const int lcol = (tid & 7) << 2;      // 0,4,...,28

    const float* Ag = A + (long long)(m0 + lrow) * lda + lcol;
    const float* Bg = B + (long long)(n0 + lrow) * ldb + lcol;
    float* sA0 = smem + lrow * LDSA + lcol;
    float* sB0 = smem + TILE_F + lrow * LDSA + lcol;

    const int kt = K >> 5;

    load_tile(Ag, lda, Bg, ldb, sA0, sB0);

    for (int it = 0; it < kt; ++it) {
        int nxt = (it + 1) & 1;
        if (it + 1 < kt) {
            load_tile(Ag + (it + 1) * BK, lda, Bg + (it + 1) * BK, ldb,
                      sA0 + nxt * BUF_STRIDE, sB0 + nxt * BUF_STRIDE);
            cp_wait<1>();
        } else {
            cp_wait<0>();
        }
        __syncthreads();
        mma_stage<CVT>(smem + (it & 1) * BUF_STRIDE,
                       smem + (it & 1) * BUF_STRIDE + TILE_F,
                       wm, wn, g, tg, acc);
        __syncthreads();
    }
}

// ---------------- Merged projection kernel ----------------
// z = 0: K -> g_k; z = 1: V -> g_vT (transposed); z = 2: Q -> g_q (grid.x < 256)
__global__ void __launch_bounds__(256, 3) proj_all_kernel(
        const float* __restrict__ query, const float* __restrict__ key,
        const float* __restrict__ value,
        const float* __restrict__ Wq, const float* __restrict__ bq,
        const float* __restrict__ Wk, const float* __restrict__ bk,
        const float* __restrict__ Wv, const float* __restrict__ bv) {
    extern __shared__ float smem[];
    const int z = blockIdx.z;
    if (z == 2 && blockIdx.x >= BATCH * NQ / BM) return;

    const float* X    = (z == 0) ? key : (z == 1) ? value : query;
    const float* W    = (z == 0) ? Wk  : (z == 1) ? Wv    : Wq;
    const float* bvec = (z == 0) ? bk  : (z == 1) ? bv    : bq;

    float acc[2][8][4] = {};
    const int m0 = blockIdx.x * BM, n0 = blockIdx.y * BN;
    gemm_loop<true>(X, DMODEL, W, DMODEL, DMODEL, m0, n0, acc, smem);

    const int tid = threadIdx.x, warp = tid >> 5, lane = tid & 31;
    const int wm = warp >> 1, wn = warp & 1, g = lane >> 2, tg = lane & 3;

#pragma unroll
    for (int mi = 0; mi < 2; mi++) {
#pragma unroll
        for (int half = 0; half < 2; half++) {
            int r = m0 + wm * 32 + mi * 16 + g + half * 8;
#pragma unroll
            for (int ni = 0; ni < 8; ni++) {
#pragma unroll
                for (int cj = 0; cj < 2; cj++) {
                    int c = n0 + wn * 64 + ni * 8 + tg * 2 + cj;
                    float v = acc[mi][ni][half * 2 + cj] + bvec[c];
                    float t = __uint_as_float(f2tf32(v));
                    if (z == 2) {
                        g_q[(long long)r * DMODEL + c] = t;
                    } else if (z == 0) {
                        g_k[(long long)r * DMODEL + c] = t;
                    } else {
                        long long bidx = r >> 11;               // NK = 2048
                        long long idx = (bidx * DMODEL + c) * NK + (r & (NK - 1));
                        g_vT[idx] = t;
                    }
                }
            }
        }
    }
}

// ---------------- Logits kernel ----------------
// e[b][q][k] = exp((q.k)/16 + bias) for live entries; 0 where key masked;
// 1 everywhere when the query row is masked (reference -> uniform softmax).
// No max subtraction needed: live logits are O(10), exp stays in fp32 range.
// Emits per-(row, ntile) partial sums for normalization.
__global__ void __launch_bounds__(256, 3) logits_kernel(const float* __restrict__ bias,
                                                        const int* __restrict__ qmask,
                                                        const int* __restrict__ kmask) {
    extern __shared__ float smem[];
    const int b = blockIdx.z;
    const int m0 = blockIdx.x * BM, n0 = blockIdx.y * BN;
    float acc[2][8][4] = {};
    gemm_loop<false>(g_q + (long long)b * NQ * DMODEL, DMODEL,
                     g_k + (long long)b * NK * DMODEL, DMODEL,
                     DMODEL, m0, n0, acc, smem);

    const float* bb = bias + (long long)b * NQ * NK;
    const int* qm = qmask + b * NQ;
    const int* km = kmask + b * NK;
    float* eb = g_e + (long long)b * NQ * NK;

    const int tid = threadIdx.x, warp = tid >> 5, lane = tid & 31;
    const int wm = warp >> 1, wn = warp & 1, g = lane >> 2, tg = lane & 3;

#pragma unroll
    for (int mi = 0; mi < 2; mi++) {
#pragma unroll
        for (int half = 0; half < 2; half++) {
            int rl = wm * 32 + mi * 16 + half * 8 + g;   // row local 0..127
            int r = m0 + rl;
            int qv = qm[r];
            float vsum = 0.f;
#pragma unroll
            for (int ni = 0; ni < 8; ni++) {
                int c = n0 + wn * 64 + ni * 8 + tg * 2;
                float l0 = acc[mi][ni][half * 2 + 0] * 0.0625f + bb[(long long)r * NK + c];
                float l1 = acc[mi][ni][half * 2 + 1] * 0.0625f + bb[(long long)r * NK + c + 1];
                float e0, e1;
                if (qv) {
                    e0 = km[c]     ? __expf(l0) : 0.f;
                    e1 = km[c + 1] ? __expf(l1) : 0.f;
                } else {
                    e0 = 1.f;   // fully-masked row -> uniform softmax
                    e1 = 1.f;
                }
                e0 = __uint_as_float(f2tf32(e0));
                e1 = __uint_as_float(f2tf32(e1));
                *reinterpret_cast<float2*>(&eb[(long long)r * NK + c]) = make_float2(e0, e1);
                vsum += e0 + e1;
            }
            // reduce across the 4 lanes (tg) sharing this row
#pragma unroll
            for (int off = 1; off <= 2; off <<= 1)
                vsum += __shfl_xor_sync(0xffffffffu, vsum, off);
            if (tg == 0) smem[wn * 128 + rl] = vsum;
        }
    }
    __syncthreads();
    if (tid < 128) {
        float S = smem[tid] + smem[128 + tid];
        int nt = blockIdx.y;
        g_psum[((b * 16 + nt) << 10) + m0 + tid] = S;
    }
}

// ---------------- Combine kernel ----------------
__global__ void __launch_bounds__(256) combine_kernel() {
    int row = blockIdx.x * 256 + threadIdx.x;      // 0..32767
    int b = row >> 10, q = row & (NQ - 1);
    float S = 0.f;
#pragma unroll
    for (int nt = 0; nt < 16; nt++)
        S += g_psum[((b * 16 + nt) << 10) + q];
    g_rowI[row] = 1.0f / S;
}

// ---------------- Output GEMM ----------------
// out[b][q][:] = invS[q] * (e[q][:] @ v). Pure NT GEMM on e; the n0==0 CTA
// also streams the final weights w = e * invS from the resident smem A-tile.
__global__ void __launch_bounds__(256, 3) out_kernel(float* __restrict__ wout,
                                                     float* __restrict__ out) {
    extern __shared__ float smem[];
    float* sI = smem + 2 * BUF_STRIDE;      // [128] row invS

    const int b = blockIdx.z;
    const int m0 = blockIdx.x * BM, n0 = blockIdx.y * BN;
    const int tid = threadIdx.x;
    const int warp = tid >> 5, lane = tid & 31;
    const int wm = warp >> 1, wn = warp & 1, g = lane >> 2, tg = lane & 3;
    const int lrow = tid >> 3;
    const int lcol = (tid & 7) << 2;

    if (tid < 128) sI[tid] = g_rowI[b * NQ + m0 + tid];

    const float* A = g_e + (long long)b * NQ * NK;      // [q][k]
    const float* B = g_vT + (long long)b * DMODEL * NK; // [d][k]
    float* wb = wout + (long long)b * NQ * NK;
    const bool write_w = (n0 == 0);

    const float* Ag = A + (long long)(m0 + lrow) * NK + lcol;
    const float* Bg = B + (long long)(n0 + lrow) * NK + lcol;
    float* sA0 = smem + lrow * LDSA + lcol;
    float* sB0 = smem + TILE_F + lrow * LDSA + lcol;

    float acc[2][8][4] = {};
    const int kt = NK / BK;   // 64

    load_tile(Ag, NK, Bg, NK, sA0, sB0);

    for (int it = 0; it < kt; ++it) {
        int nxt = (it + 1) & 1;
        if (it + 1 < kt) {
            load_tile(Ag + (it + 1) * BK, NK, Bg + (it + 1) * BK, NK,
                      sA0 + nxt * BUF_STRIDE, sB0 + nxt * BUF_STRIDE);
            cp_wait<1>();
        } else {
            cp_wait<0>();
        }
        __syncthreads();

        float* bufA = smem + (it & 1) * BUF_STRIDE;

        // Stream final weights out of the resident tile (n0==0 CTAs only).
        if (write_w) {
            const int k0 = it * BK;
#pragma unroll
            for (int rr = 0; rr < 4; rr++) {
                int row = lrow + rr * 32;
                float4 v = *reinterpret_cast<float4*>(&bufA[row * LDSA + lcol]);
                float rI = sI[row];
                v.x *= rI; v.y *= rI; v.z *= rI; v.w *= rI;
                *reinterpret_cast<float4*>(&wb[(long long)(m0 + row) * NK + k0 + lcol]) = v;
            }
        }

        mma_stage<false>(bufA, smem + (it & 1) * BUF_STRIDE + TILE_F,
                         wm, wn, g, tg, acc);
        __syncthreads();
    }

    float* ob = out + (long long)b * NQ * DMODEL;
#pragma unroll
    for (int mi = 0; mi < 2; mi++) {
#pragma unroll
        for (int half = 0; half < 2; half++) {
            int rl = wm * 32 + mi * 16 + g + half * 8;
            int r = m0 + rl;
            float rI = sI[rl];
#pragma unroll
            for (int ni = 0; ni < 8; ni++) {
#pragma unroll
                for (int cj = 0; cj < 2; cj++) {
                    int c = n0 + wn * 64 + ni * 8 + tg * 2 + cj;
                    ob[(long long)r * DMODEL + c] = acc[mi][ni][half * 2 + cj] * rI;
                }
            }
        }
    }
}

extern "C" void kernel_launch(void* const* d_in, const int* in_sizes, int n_in,
                              void* d_out, int out_size) {
    (void)in_sizes; (void)n_in; (void)out_size;
    const float* query = (const float*)d_in[0];
    const float* key   = (const float*)d_in[1];
    const float* value = (const float*)d_in[2];
    const int*   qmask = (const int*)d_in[3];
    const int*   kmask = (const int*)d_in[4];
    const float* bias  = (const float*)d_in[5];
    const float* Wq = (const float*)d_in[6];
    const float* bq = (const float*)d_in[7];
    const float* Wk = (const float*)d_in[8];
    const float* bk = (const float*)d_in[9];
    const float* Wv = (const float*)d_in[10];
    const float* bv = (const float*)d_in[11];

    float* out = (float*)d_out;                                   // (B, NQ, D)
    float* w   = out + (size_t)BATCH * NQ * DMODEL;               // (B, NQ, NK)

    cudaFuncSetAttribute((const void*)proj_all_kernel, cudaFuncAttributeMaxDynamicSharedMemorySize, SMEM_BYTES);
    cudaFuncSetAttribute((const void*)logits_kernel,   cudaFuncAttributeMaxDynamicSharedMemorySize, SMEM_BYTES);
    cudaFuncSetAttribute((const void*)out_kernel,      cudaFuncAttributeMaxDynamicSharedMemorySize, SMEM_BYTES_OUT);

    // Projections (merged): z=0 K, z=1 V(transposed), z=2 Q (x<256)
    proj_all_kernel<<<dim3(BATCH * NK / BM, DMODEL / BN, 3), 256, SMEM_BYTES>>>(
        query, key, value, Wq, bq, Wk, bk, Wv, bv);

    // Unnormalized exp(logits) + per-tile row sums
    logits_kernel<<<dim3(NQ / BM, NK / BN, BATCH), 256, SMEM_BYTES>>>(bias, qmask, kmask);

    // Fold partial sums into per-row 1/S
    combine_kernel<<<BATCH * NQ / 256, 256>>>();

    // out = invS * (e @ v); also writes w = e * invS
    out_kernel<<<dim3(NQ / BM, DMODEL / BN, BATCH), 256, SMEM_BYTES_OUT>>>(w, out);
}

// round 5
// speedup vs baseline: 1.4827x; 1.4827x over previous
#include <cuda_runtime.h>
#include <cstdint>
#include <math.h>

// Problem constants
#define BATCH 32
#define NQ    1024
#define NK    2048
#define DMODEL 256

// GEMM tiling
#define BM 128
#define BN 128
#define BK 32
#define LDSA 36                    // smem row stride (floats), conflict-free
#define TILE_F (128 * LDSA)        // floats per (A or B) tile buffer
#define BUF_STRIDE (2 * TILE_F)    // floats per double-buffer stage (A+B)
#define SMEM_BYTES (2 * BUF_STRIDE * 4)
#define SMEM_BYTES_OUT (SMEM_BYTES + 512)   // + row invS

// Scratch (static device memory — allocation-free per harness rules)
__device__ float g_q   [BATCH * NQ * DMODEL];        // tf32-rounded q
__device__ float g_k   [BATCH * NK * DMODEL];        // tf32-rounded k
__device__ float g_vT  [BATCH * DMODEL * NK];        // v transposed [b][d][k], tf32
__device__ float g_e   [(size_t)BATCH * NQ * NK];    // unnormalized exp(logits) (tf32)
__device__ float g_psum[BATCH * 16 * NQ];            // per (b, ntile, q) partial sum
__device__ float g_rowI[BATCH * NQ];                 // per row 1/sum

__device__ __forceinline__ uint32_t f2tf32(float x) {
    uint32_t r;
    asm("cvt.rna.tf32.f32 %0, %1;" : "=r"(r) : "f"(x));
    return r;
}

__device__ __forceinline__ void mma_tf32(float c[4], const uint32_t a[4], const uint32_t b[2]) {
    asm("mma.sync.aligned.m16n8k8.row.col.f32.tf32.tf32.f32 "
        "{%0,%1,%2,%3}, {%4,%5,%6,%7}, {%8,%9}, {%0,%1,%2,%3};"
        : "+f"(c[0]), "+f"(c[1]), "+f"(c[2]), "+f"(c[3])
        : "r"(a[0]), "r"(a[1]), "r"(a[2]), "r"(a[3]), "r"(b[0]), "r"(b[1]));
}

__device__ __forceinline__ void cp_async16(float* smem, const float* gmem) {
    uint32_t s = (uint32_t)__cvta_generic_to_shared(smem);
    asm volatile("cp.async.cg.shared.global [%0], [%1], 16;" :: "r"(s), "l"(gmem) : "memory");
}
__device__ __forceinline__ void cp_commit() { asm volatile("cp.async.commit_group;" ::: "memory"); }
template<int N> __device__ __forceinline__ void cp_wait() {
    asm volatile("cp.async.wait_group %0;" :: "n"(N) : "memory");
}

// Issue cp.asyncs for one 128x32 A tile and one 128x32 B tile (both [rows][K] layout).
__device__ __forceinline__ void load_tile(const float* a, long long lda,
                                          const float* b, long long ldb,
                                          float* sA, float* sB) {
#pragma unroll
    for (int r = 0; r < 128; r += 32) {
        cp_async16(sA + r * LDSA, a + (long long)r * lda);
        cp_async16(sB + r * LDSA, b + (long long)r * ldb);
    }
    cp_commit();
}

// Fragment compute for one resident 128x32 x 128x32 stage.
template<bool CVT>
__device__ __forceinline__ void mma_stage(const float* cA, const float* cB,
                                          int wm, int wn, int g, int tg,
                                          float (&acc)[2][8][4]) {
#pragma unroll
    for (int kk = 0; kk < BK; kk += 8) {
        uint32_t af[2][4];
        uint32_t bf[8][2];
#pragma unroll
        for (int mi = 0; mi < 2; mi++) {
            const float* base = cA + (wm * 32 + mi * 16 + g) * LDSA + kk + tg;
            float x0 = base[0];
            float x1 = base[8 * LDSA];
            float x2 = base[4];
            float x3 = base[8 * LDSA + 4];
            af[mi][0] = CVT ? f2tf32(x0) : __float_as_uint(x0);
            af[mi][1] = CVT ? f2tf32(x1) : __float_as_uint(x1);
            af[mi][2] = CVT ? f2tf32(x2) : __float_as_uint(x2);
            af[mi][3] = CVT ? f2tf32(x3) : __float_as_uint(x3);
        }
#pragma unroll
        for (int ni = 0; ni < 8; ni++) {
            const float* base = cB + (wn * 64 + ni * 8 + g) * LDSA + kk + tg;
            float y0 = base[0];
            float y1 = base[4];
            bf[ni][0] = CVT ? f2tf32(y0) : __float_as_uint(y0);
            bf[ni][1] = CVT ? f2tf32(y1) : __float_as_uint(y1);
        }
#pragma unroll
        for (int mi = 0; mi < 2; mi++)
#pragma unroll
            for (int ni = 0; ni < 8; ni++)
                mma_tf32(acc[mi][ni], af[mi], bf[ni]);
    }
}

// NT GEMM mainloop: acc[m][n] += sum_k A[m0+m][k] * B[n0+n][k]
template<bool CVT>
__device__ __forceinline__ void gemm_loop(const float* __restrict__ A, long long lda,
                                          const float* __restrict__ B, long long ldb,
                                          int K, int m0, int n0,
                                          float (&acc)[2][8][4], float* smem) {
    const int tid  = threadIdx.x;
    const int warp = tid >> 5, lane = tid & 31;
    const int wm = warp >> 1, wn = warp & 1;
    const int g  = lane >> 2, tg = lane & 3;
    const int lrow = tid >> 3;            // 0..31
    const int lcol = (tid & 7) << 2;      // 0,4,...,28

    const float* Ag = A + (long long)(m0 + lrow) * lda + lcol;
    const float* Bg = B + (long long)(n0 + lrow) * ldb + lcol;
    float* sA0 = smem + lrow * LDSA + lcol;
    float* sB0 = smem + TILE_F + lrow * LDSA + lcol;

    const int kt = K >> 5;

    load_tile(Ag, lda, Bg, ldb, sA0, sB0);

    for (int it = 0; it < kt; ++it) {
        int nxt = (it + 1) & 1;
        if (it + 1 < kt) {
            load_tile(Ag + (it + 1) * BK, lda, Bg + (it + 1) * BK, ldb,
                      sA0 + nxt * BUF_STRIDE, sB0 + nxt * BUF_STRIDE);
            cp_wait<1>();
        } else {
            cp_wait<0>();
        }
        __syncthreads();
        mma_stage<CVT>(smem + (it & 1) * BUF_STRIDE,
                       smem + (it & 1) * BUF_STRIDE + TILE_F,
                       wm, wn, g, tg, acc);
        __syncthreads();
    }
}

// ---------------- Merged projection kernel ----------------
// z = 0: K -> g_k; z = 1: V -> g_vT (transposed); z = 2: Q -> g_q (grid.x < 256)
__global__ void __launch_bounds__(256) proj_all_kernel(
        const float* __restrict__ query, const float* __restrict__ key,
        const float* __restrict__ value,
        const float* __restrict__ Wq, const float* __restrict__ bq,
        const float* __restrict__ Wk, const float* __restrict__ bk,
        const float* __restrict__ Wv, const float* __restrict__ bv) {
    extern __shared__ float smem[];
    const int z = blockIdx.z;
    if (z == 2 && blockIdx.x >= BATCH * NQ / BM) return;

    const float* X    = (z == 0) ? key : (z == 1) ? value : query;
    const float* W    = (z == 0) ? Wk  : (z == 1) ? Wv    : Wq;
    const float* bvec = (z == 0) ? bk  : (z == 1) ? bv    : bq;

    float acc[2][8][4] = {};
    const int m0 = blockIdx.x * BM, n0 = blockIdx.y * BN;
    gemm_loop<true>(X, DMODEL, W, DMODEL, DMODEL, m0, n0, acc, smem);

    const int tid = threadIdx.x, warp = tid >> 5, lane = tid & 31;
    const int wm = warp >> 1, wn = warp & 1, g = lane >> 2, tg = lane & 3;

#pragma unroll
    for (int mi = 0; mi < 2; mi++) {
#pragma unroll
        for (int half = 0; half < 2; half++) {
            int r = m0 + wm * 32 + mi * 16 + g + half * 8;
#pragma unroll
            for (int ni = 0; ni < 8; ni++) {
#pragma unroll
                for (int cj = 0; cj < 2; cj++) {
                    int c = n0 + wn * 64 + ni * 8 + tg * 2 + cj;
                    float v = acc[mi][ni][half * 2 + cj] + bvec[c];
                    float t = __uint_as_float(f2tf32(v));
                    if (z == 2) {
                        g_q[(long long)r * DMODEL + c] = t;
                    } else if (z == 0) {
                        g_k[(long long)r * DMODEL + c] = t;
                    } else {
                        long long bidx = r >> 11;               // NK = 2048
                        long long idx = (bidx * DMODEL + c) * NK + (r & (NK - 1));
                        g_vT[idx] = t;
                    }
                }
            }
        }
    }
}

// ---------------- Logits kernel ----------------
// e[b][q][k] = exp((q.k)/16 + bias) live; 0 where key masked; 1 everywhere when
// the query row is masked (reference -> uniform softmax). Live logits are O(10)
// so no max-subtraction is needed in fp32. Emits per-(row, ntile) partial sums.
__global__ void __launch_bounds__(256) logits_kernel(const float* __restrict__ bias,
                                                     const int* __restrict__ qmask,
                                                     const int* __restrict__ kmask) {
    extern __shared__ float smem[];
    const int b = blockIdx.z;
    const int m0 = blockIdx.x * BM, n0 = blockIdx.y * BN;
    float acc[2][8][4] = {};
    gemm_loop<false>(g_q + (long long)b * NQ * DMODEL, DMODEL,
                     g_k + (long long)b * NK * DMODEL, DMODEL,
                     DMODEL, m0, n0, acc, smem);

    const float* bb = bias + (long long)b * NQ * NK;
    const int* qm = qmask + b * NQ;
    const int* km = kmask + b * NK;
    float* eb = g_e + (long long)b * NQ * NK;

    const int tid = threadIdx.x, warp = tid >> 5, lane = tid & 31;
    const int wm = warp >> 1, wn = warp & 1, g = lane >> 2, tg = lane & 3;

#pragma unroll
    for (int mi = 0; mi < 2; mi++) {
#pragma unroll
        for (int half = 0; half < 2; half++) {
            int rl = wm * 32 + mi * 16 + half * 8 + g;   // row local 0..127
            int r = m0 + rl;
            int qv = qm[r];
            float vsum = 0.f;
#pragma unroll
            for (int ni = 0; ni < 8; ni++) {
                int c = n0 + wn * 64 + ni * 8 + tg * 2;
                float l0 = acc[mi][ni][half * 2 + 0] * 0.0625f + bb[(long long)r * NK + c];
                float l1 = acc[mi][ni][half * 2 + 1] * 0.0625f + bb[(long long)r * NK + c + 1];
                float e0, e1;
                if (qv) {
                    e0 = km[c]     ? __expf(l0) : 0.f;
                    e1 = km[c + 1] ? __expf(l1) : 0.f;
                } else {
                    e0 = 1.f;   // fully-masked row -> uniform softmax
                    e1 = 1.f;
                }
                e0 = __uint_as_float(f2tf32(e0));
                e1 = __uint_as_float(f2tf32(e1));
                *reinterpret_cast<float2*>(&eb[(long long)r * NK + c]) = make_float2(e0, e1);
                vsum += e0 + e1;
            }
            // reduce across the 4 lanes (tg) sharing this row
#pragma unroll
            for (int off = 1; off <= 2; off <<= 1)
                vsum += __shfl_xor_sync(0xffffffffu, vsum, off);
            if (tg == 0) smem[wn * 128 + rl] = vsum;
        }
    }
    __syncthreads();
    if (tid < 128) {
        float S = smem[tid] + smem[128 + tid];
        int nt = blockIdx.y;
        g_psum[((b * 16 + nt) << 10) + m0 + tid] = S;
    }
}

// ---------------- Combine kernel ----------------
__global__ void __launch_bounds__(256) combine_kernel() {
    int row = blockIdx.x * 256 + threadIdx.x;      // 0..32767
    int b = row >> 10, q = row & (NQ - 1);
    float S = 0.f;
#pragma unroll
    for (int nt = 0; nt < 16; nt++)
        S += g_psum[((b * 16 + nt) << 10) + q];
    g_rowI[row] = 1.0f / S;
}

// ---------------- Output GEMM ----------------
// out[b][q][:] = invS[q] * (e[q][:] @ v). Pure NT GEMM on e; each of the two
// column-tile CTAs streams HALF the final weights (w = e * invS) out of its
// resident smem A-tiles (n0==0 -> k<1024, n0==128 -> k>=1024): balanced,
// coalesced, overlapped with the MMA stage.
__global__ void __launch_bounds__(256) out_kernel(float* __restrict__ wout,
                                                  float* __restrict__ out) {
    extern __shared__ float smem[];
    float* sI = smem + 2 * BUF_STRIDE;      // [128] row invS

    const int b = blockIdx.z;
    const int m0 = blockIdx.x * BM, n0 = blockIdx.y * BN;
    const int tid = threadIdx.x;
    const int warp = tid >> 5, lane = tid & 31;
    const int wm = warp >> 1, wn = warp & 1, g = lane >> 2, tg = lane & 3;
    const int lrow = tid >> 3;
    const int lcol = (tid & 7) << 2;

    if (tid < 128) sI[tid] = g_rowI[b * NQ + m0 + tid];

    const float* A = g_e + (long long)b * NQ * NK;      // [q][k]
    const float* B = g_vT + (long long)b * DMODEL * NK; // [d][k]
    float* wb = wout + (long long)b * NQ * NK;
    const bool first_half = (n0 == 0);

    const float* Ag = A + (long long)(m0 + lrow) * NK + lcol;
    const float* Bg = B + (long long)(n0 + lrow) * NK + lcol;
    float* sA0 = smem + lrow * LDSA + lcol;
    float* sB0 = smem + TILE_F + lrow * LDSA + lcol;

    float acc[2][8][4] = {};
    const int kt = NK / BK;   // 64

    load_tile(Ag, NK, Bg, NK, sA0, sB0);

    for (int it = 0; it < kt; ++it) {
        int nxt = (it + 1) & 1;
        if (it + 1 < kt) {
            load_tile(Ag + (it + 1) * BK, NK, Bg + (it + 1) * BK, NK,
                      sA0 + nxt * BUF_STRIDE, sB0 + nxt * BUF_STRIDE);
            cp_wait<1>();
        } else {
            cp_wait<0>();
        }
        __syncthreads();

        float* bufA = smem + (it & 1) * BUF_STRIDE;

        // Stream this CTA's half of the final weights from the resident tile.
        if ((it < kt / 2) == first_half) {
            const int k0 = it * BK;
#pragma unroll
            for (int rr = 0; rr < 4; rr++) {
                int row = lrow + rr * 32;
                float4 v = *reinterpret_cast<float4*>(&bufA[row * LDSA + lcol]);
                float rI = sI[row];
                v.x *= rI; v.y *= rI; v.z *= rI; v.w *= rI;
                *reinterpret_cast<float4*>(&wb[(long long)(m0 + row) * NK + k0 + lcol]) = v;
            }
        }

        mma_stage<false>(bufA, smem + (it & 1) * BUF_STRIDE + TILE_F,
                         wm, wn, g, tg, acc);
        __syncthreads();
    }

    float* ob = out + (long long)b * NQ * DMODEL;
#pragma unroll
    for (int mi = 0; mi < 2; mi++) {
#pragma unroll
        for (int half = 0; half < 2; half++) {
            int rl = wm * 32 + mi * 16 + g + half * 8;
            int r = m0 + rl;
            float rI = sI[rl];
#pragma unroll
            for (int ni = 0; ni < 8; ni++) {
#pragma unroll
                for (int cj = 0; cj < 2; cj++) {
                    int c = n0 + wn * 64 + ni * 8 + tg * 2 + cj;
                    ob[(long long)r * DMODEL + c] = acc[mi][ni][half * 2 + cj] * rI;
                }
            }
        }
    }
}

extern "C" void kernel_launch(void* const* d_in, const int* in_sizes, int n_in,
                              void* d_out, int out_size) {
    (void)in_sizes; (void)n_in; (void)out_size;
    const float* query = (const float*)d_in[0];
    const float* key   = (const float*)d_in[1];
    const float* value = (const float*)d_in[2];
    const int*   qmask = (const int*)d_in[3];
    const int*   kmask = (const int*)d_in[4];
    const float* bias  = (const float*)d_in[5];
    const float* Wq = (const float*)d_in[6];
    const float* bq = (const float*)d_in[7];
    const float* Wk = (const float*)d_in[8];
    const float* bk = (const float*)d_in[9];
    const float* Wv = (const float*)d_in[10];
    const float* bv = (const float*)d_in[11];

    float* out = (float*)d_out;                                   // (B, NQ, D)
    float* w   = out + (size_t)BATCH * NQ * DMODEL;               // (B, NQ, NK)

    cudaFuncSetAttribute((const void*)proj_all_kernel, cudaFuncAttributeMaxDynamicSharedMemorySize, SMEM_BYTES);
    cudaFuncSetAttribute((const void*)logits_kernel,   cudaFuncAttributeMaxDynamicSharedMemorySize, SMEM_BYTES);
    cudaFuncSetAttribute((const void*)out_kernel,      cudaFuncAttributeMaxDynamicSharedMemorySize, SMEM_BYTES_OUT);

    // Projections (merged): z=0 K, z=1 V(transposed), z=2 Q (x<256)
    proj_all_kernel<<<dim3(BATCH * NK / BM, DMODEL / BN, 3), 256, SMEM_BYTES>>>(
        query, key, value, Wq, bq, Wk, bk, Wv, bv);

    // Unnormalized exp(logits) + per-tile row sums
    logits_kernel<<<dim3(NQ / BM, NK / BN, BATCH), 256, SMEM_BYTES>>>(bias, qmask, kmask);

    // Fold partial sums into per-row 1/S
    combine_kernel<<<BATCH * NQ / 256, 256>>>();

    // out = invS * (e @ v); also streams w = e * invS (half per column-tile CTA)
    out_kernel<<<dim3(NQ / BM, DMODEL / BN, BATCH), 256, SMEM_BYTES_OUT>>>(w, out);
}